// round 16
// baseline (speedup 1.0000x reference)
#include <cuda_runtime.h>
#include <cuda_bf16.h>
#include <math.h>
#include <stdint.h>

#define B_   32
#define N_   3136
#define D_   384
#define H_   8
#define C_   48
#define E_   1152            // 3*D
#define M_   (B_*N_)         // 100352
#define BH_  (B_*H_)         // 256
#define CH_  12              // K chunks of 32 (384/32)

// ---- scratch (static device allocations; no runtime allocs) ----
__device__ float g_q[(size_t)BH_*C_*N_];     // (B,H,C,N)
__device__ float g_k[(size_t)BH_*C_*N_];
__device__ float g_v[(size_t)BH_*C_*N_];
__device__ float g_invq[BH_*C_];
__device__ float g_invk[BH_*C_];
__device__ float g_attn[(size_t)BH_*C_*C_];
// packed hi/lo bf16, layout [row][12 chunks][64]: chunk = [32 hi | 32 lo]
__device__ __nv_bfloat16 g_xp [(size_t)M_*768];
__device__ __nv_bfloat16 g_wp [(size_t)E_*768];
__device__ __nv_bfloat16 g_pwp[(size_t)D_*768];
__device__ __nv_bfloat16 g_op [(size_t)M_*768];

// ============================================================
// helpers
// ============================================================
__device__ __forceinline__ uint32_t smem_u32(const void* p) {
    uint32_t a;
    asm("{ .reg .u64 t; cvta.to.shared.u64 t, %1; cvt.u32.u64 %0, t; }" : "=r"(a) : "l"(p));
    return a;
}
__device__ __forceinline__ void ldsm4(uint32_t* r, uint32_t a) {
    asm volatile("ldmatrix.sync.aligned.m8n8.x4.shared.b16 {%0,%1,%2,%3}, [%4];"
                 : "=r"(r[0]), "=r"(r[1]), "=r"(r[2]), "=r"(r[3]) : "r"(a));
}
__device__ __forceinline__ void mma16816(float* c, const uint32_t* a,
                                         uint32_t b0, uint32_t b1) {
    asm volatile("mma.sync.aligned.m16n8k16.row.col.f32.bf16.bf16.f32 "
                 "{%0,%1,%2,%3}, {%4,%5,%6,%7}, {%8,%9}, {%0,%1,%2,%3};"
                 : "+f"(c[0]), "+f"(c[1]), "+f"(c[2]), "+f"(c[3])
                 : "r"(a[0]), "r"(a[1]), "r"(a[2]), "r"(a[3]), "r"(b0), "r"(b1));
}

#define TILE_BYTES 16384
#define SMEM_BYTES (2*TILE_BYTES)

__device__ __forceinline__ uint32_t sw_addr(uint32_t base, int row, int unit) {
    return base + row * 128 + (((unit) ^ (row & 7)) << 4);
}

// ============================================================
// K0: split fp32 -> packed hi/lo bf16 chunks (which: 0=x,1=w,2=pw)
// one thread per float4
// ============================================================
__global__ __launch_bounds__(256) void k0_split(const float* __restrict__ src,
                                                int which, int n4) {
    int idx = blockIdx.x * 256 + threadIdx.x;
    if (idx >= n4) return;
    __nv_bfloat16* dst = (which == 0) ? g_xp : ((which == 1) ? g_wp : g_pwp);
    float4 v = ((const float4*)src)[idx];
    int chunk = idx >> 3, q4 = idx & 7;
    __nv_bfloat162 h0 = __floats2bfloat162_rn(v.x, v.y);
    __nv_bfloat162 h1 = __floats2bfloat162_rn(v.z, v.w);
    float2 f0 = __bfloat1622float2(h0), f1 = __bfloat1622float2(h1);
    __nv_bfloat162 l0 = __floats2bfloat162_rn(v.x - f0.x, v.y - f0.y);
    __nv_bfloat162 l1 = __floats2bfloat162_rn(v.z - f1.x, v.w - f1.y);
    uint2 hv, lv;
    hv.x = *reinterpret_cast<uint32_t*>(&h0);
    hv.y = *reinterpret_cast<uint32_t*>(&h1);
    lv.x = *reinterpret_cast<uint32_t*>(&l0);
    lv.y = *reinterpret_cast<uint32_t*>(&l1);
    __nv_bfloat16* base = dst + (size_t)chunk * 64;
    *(uint2*)(base + q4 * 4)      = hv;
    *(uint2*)(base + 32 + q4 * 4) = lv;
}

// ============================================================
// GEMM mainloop on packed bf16 inputs, register-prefetched.
// C[128m x 128e] = A * B^T, 3-product hi/lo compensation.
// 8 warps: wm = wid&3 (32-row strip), wn = wid>>2 (64-col strip).
// ============================================================
__device__ __forceinline__ void gemm_main(const __nv_bfloat16* __restrict__ Ap,
                                          const __nv_bfloat16* __restrict__ Bp,
                                          char* smem, uint32_t sb,
                                          float acc[2][8][4]) {
    const int tid = threadIdx.x;
    const int lane = tid & 31, wid = tid >> 5;
    const int wm = wid & 3, wn = wid >> 2;
    const int lr = lane & 15, lu = lane >> 4;

    uint4 ra[4], rb[4];
#define PREF(ktv)                                                              \
    {                                                                          \
        _Pragma("unroll")                                                      \
        for (int t = 0; t < 4; t++) {                                          \
            int item = tid + t * 256;                                          \
            int row = item >> 3, u = item & 7;                                 \
            size_t o = ((size_t)row * CH_ + (ktv)) * 64 + u * 8;               \
            ra[t] = *(const uint4*)(Ap + o);                                   \
            rb[t] = *(const uint4*)(Bp + o);                                   \
        }                                                                      \
    }
    PREF(0);

    for (int kt = 0; kt < CH_; kt++) {
        if (kt) __syncthreads();
        #pragma unroll
        for (int t = 0; t < 4; t++) {
            int item = tid + t * 256;
            int row = item >> 3, u = item & 7;
            uint32_t off = row * 128 + ((u ^ (row & 7)) << 4);
            *(uint4*)(smem + off)              = ra[t];
            *(uint4*)(smem + TILE_BYTES + off) = rb[t];
        }
        __syncthreads();
        if (kt + 1 < CH_) PREF(kt + 1);

        #pragma unroll
        for (int ks = 0; ks < 2; ks++) {
            uint32_t ah[2][4], al[2][4];
            #pragma unroll
            for (int mt = 0; mt < 2; mt++) {
                int r = wm * 32 + lr + mt * 16;
                ldsm4(ah[mt], sw_addr(sb, r, ks * 2 + lu));
                ldsm4(al[mt], sw_addr(sb, r, 4 + ks * 2 + lu));
            }
            #pragma unroll
            for (int nb = 0; nb < 4; nb++) {
                uint32_t bh[4], bl[4];
                int r = wn * 64 + lr + nb * 16;
                ldsm4(bh, sw_addr(sb + TILE_BYTES, r, ks * 2 + lu));
                ldsm4(bl, sw_addr(sb + TILE_BYTES, r, 4 + ks * 2 + lu));
                #pragma unroll
                for (int mt = 0; mt < 2; mt++) {
                    #pragma unroll
                    for (int hf = 0; hf < 2; hf++) {
                        float* c = acc[mt][nb * 2 + hf];
                        mma16816(c, ah[mt], bh[hf], bh[2 + hf]);
                        mma16816(c, ah[mt], bl[hf], bl[2 + hf]);
                        mma16816(c, al[mt], bh[hf], bh[2 + hf]);
                    }
                }
            }
        }
    }
#undef PREF
}

// ============================================================
// K1: qkv GEMM, scatter into q/k/v (B,H,C,N). grid (9, 784)
// ============================================================
__global__ __launch_bounds__(256) void k1_mma() {
    __shared__ __align__(128) char smem[SMEM_BYTES];
    uint32_t sb = smem_u32(smem);
    float acc[2][8][4];
    #pragma unroll
    for (int i = 0; i < 2; i++)
        #pragma unroll
        for (int j = 0; j < 8; j++)
            #pragma unroll
            for (int kk = 0; kk < 4; kk++) acc[i][j][kk] = 0.f;

    const int e0 = blockIdx.x * 128;
    const int m0 = blockIdx.y * 128;
    gemm_main(g_xp + (size_t)m0 * 768, g_wp + (size_t)e0 * 768, smem, sb, acc);

    const int tid = threadIdx.x, lane = tid & 31, wid = tid >> 5;
    const int wm = wid & 3, wn = wid >> 2;
    const int lq = lane >> 2, le = (lane & 3) * 2;
    const int t = e0 / D_;              // uniform per block (384 % 128 == 0)
    float* dst = (t == 0) ? g_q : ((t == 1) ? g_k : g_v);
    const int ebase = e0 - t * D_ + wn * 64 + le;

    #pragma unroll
    for (int mt = 0; mt < 2; mt++) {
        int rowl = wm * 32 + mt * 16 + lq;
        #pragma unroll
        for (int rr = 0; rr < 2; rr++) {
            int m = m0 + rowl + rr * 8;
            int bb = m / N_;
            int n = m - bb * N_;
            #pragma unroll
            for (int nt = 0; nt < 8; nt++) {
                int el = ebase + nt * 8;
                int h = el / C_;
                int c = el - h * C_;
                float* p = dst + ((size_t)(bb * H_ + h) * C_ + c) * N_ + n;
                p[0]  = acc[mt][nt][rr * 2 + 0];
                p[N_] = acc[mt][nt][rr * 2 + 1];
            }
        }
    }
}

// ============================================================
// K5: y = o @ proj_w^T + proj_b. grid (3, 784)
// ============================================================
__global__ __launch_bounds__(256) void k5_mma(const float* __restrict__ pb,
                                              float* __restrict__ y) {
    __shared__ __align__(128) char smem[SMEM_BYTES];
    uint32_t sb = smem_u32(smem);
    float acc[2][8][4];
    #pragma unroll
    for (int i = 0; i < 2; i++)
        #pragma unroll
        for (int j = 0; j < 8; j++)
            #pragma unroll
            for (int kk = 0; kk < 4; kk++) acc[i][j][kk] = 0.f;

    const int e0 = blockIdx.x * 128;
    const int m0 = blockIdx.y * 128;
    gemm_main(g_op + (size_t)m0 * 768, g_pwp + (size_t)e0 * 768, smem, sb, acc);

    const int tid = threadIdx.x, lane = tid & 31, wid = tid >> 5;
    const int wm = wid & 3, wn = wid >> 2;
    const int lq = lane >> 2, le = (lane & 3) * 2;

    #pragma unroll
    for (int mt = 0; mt < 2; mt++) {
        int rowl = wm * 32 + mt * 16 + lq;
        #pragma unroll
        for (int rr = 0; rr < 2; rr++) {
            int m = m0 + rowl + rr * 8;
            float* yp = y + (size_t)m * D_ + e0;
            #pragma unroll
            for (int nt = 0; nt < 8; nt++) {
                int col = wn * 64 + nt * 8 + le;
                float2 o;
                o.x = acc[mt][nt][rr * 2 + 0] + pb[e0 + col];
                o.y = acc[mt][nt][rr * 2 + 1] + pb[e0 + col + 1];
                *(float2*)(yp + col) = o;
            }
        }
    }
}

// ============================================================
// K2: inverse L2 norms of q,k rows (reduce over N). One warp/row.
// ============================================================
__global__ __launch_bounds__(256) void k2_norms() {
    const int gwarp = (blockIdx.x * blockDim.x + threadIdx.x) >> 5;
    const int lane  = threadIdx.x & 31;
    const int total = BH_ * C_;
    if (gwarp >= 2 * total) return;
    const bool is_q = (gwarp < total);
    const int row = is_q ? gwarp : (gwarp - total);
    const float* p = (is_q ? g_q : g_k) + (size_t)row * N_;
    float s = 0.f;
    for (int i = lane; i < N_; i += 32) { float v = p[i]; s += v * v; }
    #pragma unroll
    for (int off = 16; off; off >>= 1) s += __shfl_xor_sync(0xffffffffu, s, off);
    if (lane == 0) {
        float inv = 1.f / fmaxf(sqrtf(s), 1e-12f);
        (is_q ? g_invq : g_invk)[row] = inv;
    }
}

// ============================================================
// K3: attn[b,h] = softmax( (q_hat @ k_hat^T) * temp[h] )  (48x48, K=3136)
// ============================================================
__global__ __launch_bounds__(256) void k3_attn(const float* __restrict__ temperature) {
    __shared__ float qs[48][68];
    __shared__ float ks[48][68];
    __shared__ float Ss[48][49];
    const int bh = blockIdx.x;
    const int h  = bh & (H_ - 1);
    const int tid = threadIdx.x;
    const int tx = tid & 15;    // -> d
    const int ty = tid >> 4;    // -> c
    const float* qp = g_q + (size_t)bh * C_ * N_;
    const float* kp = g_k + (size_t)bh * C_ * N_;

    float acc[3][3];
    #pragma unroll
    for (int i = 0; i < 3; i++)
        #pragma unroll
        for (int j = 0; j < 3; j++) acc[i][j] = 0.f;

    for (int n0 = 0; n0 < N_; n0 += 64) {
        #pragma unroll
        for (int it = 0; it < 3; it++) {
            int item = tid + it * 256;
            int row = item >> 4;
            int c4  = (item & 15) * 4;
            float4 a = *(const float4*)(qp + (size_t)row * N_ + n0 + c4);
            float4 b = *(const float4*)(kp + (size_t)row * N_ + n0 + c4);
            *(float4*)&qs[row][c4] = a;
            *(float4*)&ks[row][c4] = b;
        }
        __syncthreads();
        #pragma unroll 4
        for (int nn = 0; nn < 64; nn++) {
            float qr[3], kr[3];
            #pragma unroll
            for (int i = 0; i < 3; i++) qr[i] = qs[ty * 3 + i][nn];
            #pragma unroll
            for (int j = 0; j < 3; j++) kr[j] = ks[tx * 3 + j][nn];
            #pragma unroll
            for (int i = 0; i < 3; i++)
                #pragma unroll
                for (int j = 0; j < 3; j++)
                    acc[i][j] += qr[i] * kr[j];
        }
        __syncthreads();
    }

    const float temp = temperature[h];
    #pragma unroll
    for (int i = 0; i < 3; i++) {
        int c = ty * 3 + i;
        float iq = g_invq[bh * C_ + c] * temp;
        #pragma unroll
        for (int j = 0; j < 3; j++) {
            int d = tx * 3 + j;
            Ss[c][d] = acc[i][j] * iq * g_invk[bh * C_ + d];
        }
    }
    __syncthreads();

    if (tid < C_) {
        const int c = tid;
        float mx = -INFINITY;
        for (int d = 0; d < C_; d++) mx = fmaxf(mx, Ss[c][d]);
        float sum = 0.f;
        for (int d = 0; d < C_; d++) sum += expf(Ss[c][d] - mx);
        float inv = 1.f / sum;
        float* out = g_attn + ((size_t)bh * C_ + c) * C_;
        for (int d = 0; d < C_; d++) out[d] = expf(Ss[c][d] - mx) * inv;
    }
}

// ============================================================
// K4: out = attn @ v; register-blocked (16c x 4n per thread).
// Writes o directly in packed hi/lo bf16 layout for k5.
// grid (13, 256), 192 threads (ty=c-group of 16, tx=4 tokens)
// ============================================================
__global__ __launch_bounds__(192) void k4_av() {
    __shared__ float At[48][48];    // At[d][c] (transposed attn)
    const int bh = blockIdx.y;
    const int b = bh >> 3, h = bh & 7;
    const int tid = threadIdx.x;
    for (int i = tid; i < C_ * C_; i += 192) {
        int c = i / C_, d = i - (i / C_) * C_;
        At[d][c] = g_attn[(size_t)bh * C_ * C_ + i];
    }
    __syncthreads();

    const int ty = tid / 64;          // 0..2  -> c range [ty*16, ty*16+16)
    const int tx = tid - ty * 64;     // 0..63 -> tokens n0..n0+3
    const int n0 = blockIdx.x * 256 + tx * 4;
    if (n0 >= N_) return;

    const float* vp = g_v + (size_t)bh * C_ * N_ + n0;
    const int cb = ty * 16;
    float acc[16][4];
    #pragma unroll
    for (int c = 0; c < 16; c++)
        #pragma unroll
        for (int j = 0; j < 4; j++) acc[c][j] = 0.f;

    for (int d = 0; d < C_; d++) {
        float4 v4 = *(const float4*)(vp + (size_t)d * N_);
        float4 a0 = *(const float4*)&At[d][cb];
        float4 a1 = *(const float4*)&At[d][cb + 4];
        float4 a2 = *(const float4*)&At[d][cb + 8];
        float4 a3 = *(const float4*)&At[d][cb + 12];
        float as[16] = {a0.x,a0.y,a0.z,a0.w, a1.x,a1.y,a1.z,a1.w,
                        a2.x,a2.y,a2.z,a2.w, a3.x,a3.y,a3.z,a3.w};
        #pragma unroll
        for (int c = 0; c < 16; c++) {
            acc[c][0] += as[c] * v4.x;
            acc[c][1] += as[c] * v4.y;
            acc[c][2] += as[c] * v4.z;
            acc[c][3] += as[c] * v4.w;
        }
    }

    // write packed hi/lo bf16 into g_op for k5
    const int e0 = h * C_ + cb;       // multiple of 16
    const int chunk = e0 >> 5;
    const int off = e0 & 31;          // 0 or 16
    #pragma unroll
    for (int j = 0; j < 4; j++) {
        size_t m = (size_t)b * N_ + n0 + j;
        uint32_t hi[8], lo[8];
        #pragma unroll
        for (int p = 0; p < 8; p++) {
            float x0 = acc[2 * p][j], x1 = acc[2 * p + 1][j];
            __nv_bfloat162 hh = __floats2bfloat162_rn(x0, x1);
            float2 hf = __bfloat1622float2(hh);
            __nv_bfloat162 ll = __floats2bfloat162_rn(x0 - hf.x, x1 - hf.y);
            hi[p] = *reinterpret_cast<uint32_t*>(&hh);
            lo[p] = *reinterpret_cast<uint32_t*>(&ll);
        }
        __nv_bfloat16* base = g_op + m * 768 + chunk * 64;
        *(uint4*)(base + off)          = *(uint4*)&hi[0];
        *(uint4*)(base + off + 8)      = *(uint4*)&hi[4];
        *(uint4*)(base + 32 + off)     = *(uint4*)&lo[0];
        *(uint4*)(base + 32 + off + 8) = *(uint4*)&lo[4];
    }
}

// ============================================================
extern "C" void kernel_launch(void* const* d_in, const int* in_sizes, int n_in,
                              void* d_out, int out_size) {
    const float* x           = (const float*)d_in[0];
    const float* qkv_w       = (const float*)d_in[1];
    const float* temperature = (const float*)d_in[2];
    const float* proj_w      = (const float*)d_in[3];
    const float* proj_b      = (const float*)d_in[4];
    float* y = (float*)d_out;

    k0_split<<<(M_ * 96 + 255) / 256, 256>>>(x, 0, M_ * 96);
    k0_split<<<(E_ * 96 + 255) / 256, 256>>>(qkv_w, 1, E_ * 96);
    k0_split<<<(D_ * 96 + 255) / 256, 256>>>(proj_w, 2, D_ * 96);
    k1_mma<<<dim3(E_ / 128, M_ / 128), 256>>>();                 // (9, 784)
    k2_norms<<<(2 * BH_ * C_ + 7) / 8, 256>>>();
    k3_attn<<<BH_, 256>>>(temperature);
    k4_av<<<dim3((N_ + 255) / 256, BH_), 192>>>();               // (13, 256)
    k5_mma<<<dim3(D_ / 128, M_ / 128), 256>>>(proj_b, y);        // (3, 784)
}

// round 17
// speedup vs baseline: 1.0080x; 1.0080x over previous
#include <cuda_runtime.h>
#include <cuda_bf16.h>
#include <math.h>
#include <stdint.h>

#define B_   32
#define N_   3136
#define D_   384
#define H_   8
#define C_   48
#define E_   1152            // 3*D
#define M_   (B_*N_)         // 100352
#define BH_  (B_*H_)         // 256
#define CH_  12              // K chunks of 32 (384/32)

// ---- scratch (static device allocations; no runtime allocs) ----
__device__ float g_q[(size_t)BH_*C_*N_];     // (B,H,C,N)
__device__ float g_k[(size_t)BH_*C_*N_];
__device__ float g_v[(size_t)BH_*C_*N_];
__device__ float g_invq[BH_*C_];
__device__ float g_invk[BH_*C_];
__device__ float g_attn[(size_t)BH_*C_*C_];
// packed hi/lo bf16, layout [row][12 chunks][64]: chunk = [32 hi | 32 lo]
__device__ __nv_bfloat16 g_xp [(size_t)M_*768];
__device__ __nv_bfloat16 g_wp [(size_t)E_*768];
__device__ __nv_bfloat16 g_pwp[(size_t)D_*768];
__device__ __nv_bfloat16 g_op [(size_t)M_*768];

// ============================================================
// helpers
// ============================================================
__device__ __forceinline__ uint32_t smem_u32(const void* p) {
    uint32_t a;
    asm("{ .reg .u64 t; cvta.to.shared.u64 t, %1; cvt.u32.u64 %0, t; }" : "=r"(a) : "l"(p));
    return a;
}
__device__ __forceinline__ void ldsm4(uint32_t* r, uint32_t a) {
    asm volatile("ldmatrix.sync.aligned.m8n8.x4.shared.b16 {%0,%1,%2,%3}, [%4];"
                 : "=r"(r[0]), "=r"(r[1]), "=r"(r[2]), "=r"(r[3]) : "r"(a));
}
__device__ __forceinline__ void mma16816(float* c, const uint32_t* a,
                                         uint32_t b0, uint32_t b1) {
    asm volatile("mma.sync.aligned.m16n8k16.row.col.f32.bf16.bf16.f32 "
                 "{%0,%1,%2,%3}, {%4,%5,%6,%7}, {%8,%9}, {%0,%1,%2,%3};"
                 : "+f"(c[0]), "+f"(c[1]), "+f"(c[2]), "+f"(c[3])
                 : "r"(a[0]), "r"(a[1]), "r"(a[2]), "r"(a[3]), "r"(b0), "r"(b1));
}

#define TILE_BYTES 16384
#define SMEM_BYTES (2*TILE_BYTES)

__device__ __forceinline__ uint32_t sw_addr(uint32_t base, int row, int unit) {
    return base + row * 128 + (((unit) ^ (row & 7)) << 4);
}

// ============================================================
// K0: split fp32 -> packed hi/lo bf16 chunks (which: 0=x,1=w,2=pw)
// one thread per float4
// ============================================================
__global__ __launch_bounds__(256) void k0_split(const float* __restrict__ src,
                                                int which, int n4) {
    int idx = blockIdx.x * 256 + threadIdx.x;
    if (idx >= n4) return;
    __nv_bfloat16* dst = (which == 0) ? g_xp : ((which == 1) ? g_wp : g_pwp);
    float4 v = ((const float4*)src)[idx];
    int chunk = idx >> 3, q4 = idx & 7;
    __nv_bfloat162 h0 = __floats2bfloat162_rn(v.x, v.y);
    __nv_bfloat162 h1 = __floats2bfloat162_rn(v.z, v.w);
    float2 f0 = __bfloat1622float2(h0), f1 = __bfloat1622float2(h1);
    __nv_bfloat162 l0 = __floats2bfloat162_rn(v.x - f0.x, v.y - f0.y);
    __nv_bfloat162 l1 = __floats2bfloat162_rn(v.z - f1.x, v.w - f1.y);
    uint2 hv, lv;
    hv.x = *reinterpret_cast<uint32_t*>(&h0);
    hv.y = *reinterpret_cast<uint32_t*>(&h1);
    lv.x = *reinterpret_cast<uint32_t*>(&l0);
    lv.y = *reinterpret_cast<uint32_t*>(&l1);
    __nv_bfloat16* base = dst + (size_t)chunk * 64;
    *(uint2*)(base + q4 * 4)      = hv;
    *(uint2*)(base + 32 + q4 * 4) = lv;
}

// ============================================================
// GEMM mainloop on packed bf16 inputs, register-prefetched.
// C[128m x 128e] = A * B^T, 3-product hi/lo compensation.
// 8 warps: wm = wid&3 (32-row strip), wn = wid>>2 (64-col strip).
// ============================================================
__device__ __forceinline__ void gemm_main(const __nv_bfloat16* __restrict__ Ap,
                                          const __nv_bfloat16* __restrict__ Bp,
                                          char* smem, uint32_t sb,
                                          float acc[2][8][4]) {
    const int tid = threadIdx.x;
    const int lane = tid & 31, wid = tid >> 5;
    const int wm = wid & 3, wn = wid >> 2;
    const int lr = lane & 15, lu = lane >> 4;

    uint4 ra[4], rb[4];
#define PREF(ktv)                                                              \
    {                                                                          \
        _Pragma("unroll")                                                      \
        for (int t = 0; t < 4; t++) {                                          \
            int item = tid + t * 256;                                          \
            int row = item >> 3, u = item & 7;                                 \
            size_t o = ((size_t)row * CH_ + (ktv)) * 64 + u * 8;               \
            ra[t] = *(const uint4*)(Ap + o);                                   \
            rb[t] = *(const uint4*)(Bp + o);                                   \
        }                                                                      \
    }
    PREF(0);

    for (int kt = 0; kt < CH_; kt++) {
        if (kt) __syncthreads();
        #pragma unroll
        for (int t = 0; t < 4; t++) {
            int item = tid + t * 256;
            int row = item >> 3, u = item & 7;
            uint32_t off = row * 128 + ((u ^ (row & 7)) << 4);
            *(uint4*)(smem + off)              = ra[t];
            *(uint4*)(smem + TILE_BYTES + off) = rb[t];
        }
        __syncthreads();
        if (kt + 1 < CH_) PREF(kt + 1);

        #pragma unroll
        for (int ks = 0; ks < 2; ks++) {
            uint32_t ah[2][4], al[2][4];
            #pragma unroll
            for (int mt = 0; mt < 2; mt++) {
                int r = wm * 32 + lr + mt * 16;
                ldsm4(ah[mt], sw_addr(sb, r, ks * 2 + lu));
                ldsm4(al[mt], sw_addr(sb, r, 4 + ks * 2 + lu));
            }
            #pragma unroll
            for (int nb = 0; nb < 4; nb++) {
                uint32_t bh[4], bl[4];
                int r = wn * 64 + lr + nb * 16;
                ldsm4(bh, sw_addr(sb + TILE_BYTES, r, ks * 2 + lu));
                ldsm4(bl, sw_addr(sb + TILE_BYTES, r, 4 + ks * 2 + lu));
                #pragma unroll
                for (int mt = 0; mt < 2; mt++) {
                    #pragma unroll
                    for (int hf = 0; hf < 2; hf++) {
                        float* c = acc[mt][nb * 2 + hf];
                        mma16816(c, ah[mt], bh[hf], bh[2 + hf]);
                        mma16816(c, ah[mt], bl[hf], bl[2 + hf]);
                        mma16816(c, al[mt], bh[hf], bh[2 + hf]);
                    }
                }
            }
        }
    }
#undef PREF
}

// ============================================================
// K1: qkv GEMM, scatter into q/k/v (B,H,C,N). grid (9, 784)
// ============================================================
__global__ __launch_bounds__(256) void k1_mma() {
    __shared__ __align__(128) char smem[SMEM_BYTES];
    uint32_t sb = smem_u32(smem);
    float acc[2][8][4];
    #pragma unroll
    for (int i = 0; i < 2; i++)
        #pragma unroll
        for (int j = 0; j < 8; j++)
            #pragma unroll
            for (int kk = 0; kk < 4; kk++) acc[i][j][kk] = 0.f;

    const int e0 = blockIdx.x * 128;
    const int m0 = blockIdx.y * 128;
    gemm_main(g_xp + (size_t)m0 * 768, g_wp + (size_t)e0 * 768, smem, sb, acc);

    const int tid = threadIdx.x, lane = tid & 31, wid = tid >> 5;
    const int wm = wid & 3, wn = wid >> 2;
    const int lq = lane >> 2, le = (lane & 3) * 2;
    const int t = e0 / D_;              // uniform per block (384 % 128 == 0)
    float* dst = (t == 0) ? g_q : ((t == 1) ? g_k : g_v);
    const int ebase = e0 - t * D_ + wn * 64 + le;

    #pragma unroll
    for (int mt = 0; mt < 2; mt++) {
        int rowl = wm * 32 + mt * 16 + lq;
        #pragma unroll
        for (int rr = 0; rr < 2; rr++) {
            int m = m0 + rowl + rr * 8;
            int bb = m / N_;
            int n = m - bb * N_;
            #pragma unroll
            for (int nt = 0; nt < 8; nt++) {
                int el = ebase + nt * 8;
                int h = el / C_;
                int c = el - h * C_;
                float* p = dst + ((size_t)(bb * H_ + h) * C_ + c) * N_ + n;
                p[0]  = acc[mt][nt][rr * 2 + 0];
                p[N_] = acc[mt][nt][rr * 2 + 1];
            }
        }
    }
}

// ============================================================
// K5: y = o @ proj_w^T + proj_b. grid (3, 784)
// ============================================================
__global__ __launch_bounds__(256) void k5_mma(const float* __restrict__ pb,
                                              float* __restrict__ y) {
    __shared__ __align__(128) char smem[SMEM_BYTES];
    uint32_t sb = smem_u32(smem);
    float acc[2][8][4];
    #pragma unroll
    for (int i = 0; i < 2; i++)
        #pragma unroll
        for (int j = 0; j < 8; j++)
            #pragma unroll
            for (int kk = 0; kk < 4; kk++) acc[i][j][kk] = 0.f;

    const int e0 = blockIdx.x * 128;
    const int m0 = blockIdx.y * 128;
    gemm_main(g_op + (size_t)m0 * 768, g_pwp + (size_t)e0 * 768, smem, sb, acc);

    const int tid = threadIdx.x, lane = tid & 31, wid = tid >> 5;
    const int wm = wid & 3, wn = wid >> 2;
    const int lq = lane >> 2, le = (lane & 3) * 2;

    #pragma unroll
    for (int mt = 0; mt < 2; mt++) {
        int rowl = wm * 32 + mt * 16 + lq;
        #pragma unroll
        for (int rr = 0; rr < 2; rr++) {
            int m = m0 + rowl + rr * 8;
            float* yp = y + (size_t)m * D_ + e0;
            #pragma unroll
            for (int nt = 0; nt < 8; nt++) {
                int col = wn * 64 + nt * 8 + le;
                float2 o;
                o.x = acc[mt][nt][rr * 2 + 0] + pb[e0 + col];
                o.y = acc[mt][nt][rr * 2 + 1] + pb[e0 + col + 1];
                *(float2*)(yp + col) = o;
            }
        }
    }
}

// ============================================================
// K2: inverse L2 norms of q,k rows (reduce over N). One warp/row.
// ============================================================
__global__ __launch_bounds__(256) void k2_norms() {
    const int gwarp = (blockIdx.x * blockDim.x + threadIdx.x) >> 5;
    const int lane  = threadIdx.x & 31;
    const int total = BH_ * C_;
    if (gwarp >= 2 * total) return;
    const bool is_q = (gwarp < total);
    const int row = is_q ? gwarp : (gwarp - total);
    const float* p = (is_q ? g_q : g_k) + (size_t)row * N_;
    float s = 0.f;
    for (int i = lane; i < N_; i += 32) { float v = p[i]; s += v * v; }
    #pragma unroll
    for (int off = 16; off; off >>= 1) s += __shfl_xor_sync(0xffffffffu, s, off);
    if (lane == 0) {
        float inv = 1.f / fmaxf(sqrtf(s), 1e-12f);
        (is_q ? g_invq : g_invk)[row] = inv;
    }
}

// ============================================================
// K3: attn[b,h] = softmax( (q_hat @ k_hat^T) * temp[h] )  (48x48, K=3136)
// ============================================================
__global__ __launch_bounds__(256) void k3_attn(const float* __restrict__ temperature) {
    __shared__ float qs[48][68];
    __shared__ float ks[48][68];
    __shared__ float Ss[48][49];
    const int bh = blockIdx.x;
    const int h  = bh & (H_ - 1);
    const int tid = threadIdx.x;
    const int tx = tid & 15;    // -> d
    const int ty = tid >> 4;    // -> c
    const float* qp = g_q + (size_t)bh * C_ * N_;
    const float* kp = g_k + (size_t)bh * C_ * N_;

    float acc[3][3];
    #pragma unroll
    for (int i = 0; i < 3; i++)
        #pragma unroll
        for (int j = 0; j < 3; j++) acc[i][j] = 0.f;

    for (int n0 = 0; n0 < N_; n0 += 64) {
        #pragma unroll
        for (int it = 0; it < 3; it++) {
            int item = tid + it * 256;
            int row = item >> 4;
            int c4  = (item & 15) * 4;
            float4 a = *(const float4*)(qp + (size_t)row * N_ + n0 + c4);
            float4 b = *(const float4*)(kp + (size_t)row * N_ + n0 + c4);
            *(float4*)&qs[row][c4] = a;
            *(float4*)&ks[row][c4] = b;
        }
        __syncthreads();
        #pragma unroll 4
        for (int nn = 0; nn < 64; nn++) {
            float qr[3], kr[3];
            #pragma unroll
            for (int i = 0; i < 3; i++) qr[i] = qs[ty * 3 + i][nn];
            #pragma unroll
            for (int j = 0; j < 3; j++) kr[j] = ks[tx * 3 + j][nn];
            #pragma unroll
            for (int i = 0; i < 3; i++)
                #pragma unroll
                for (int j = 0; j < 3; j++)
                    acc[i][j] += qr[i] * kr[j];
        }
        __syncthreads();
    }

    const float temp = temperature[h];
    #pragma unroll
    for (int i = 0; i < 3; i++) {
        int c = ty * 3 + i;
        float iq = g_invq[bh * C_ + c] * temp;
        #pragma unroll
        for (int j = 0; j < 3; j++) {
            int d = tx * 3 + j;
            Ss[c][d] = acc[i][j] * iq * g_invk[bh * C_ + d];
        }
    }
    __syncthreads();

    if (tid < C_) {
        const int c = tid;
        float mx = -INFINITY;
        for (int d = 0; d < C_; d++) mx = fmaxf(mx, Ss[c][d]);
        float sum = 0.f;
        for (int d = 0; d < C_; d++) sum += expf(Ss[c][d] - mx);
        float inv = 1.f / sum;
        float* out = g_attn + ((size_t)bh * C_ + c) * C_;
        for (int d = 0; d < C_; d++) out[d] = expf(Ss[c][d] - mx) * inv;
    }
}

// ============================================================
// K4: out = attn @ v; register-blocked (16c x 4n per thread).
// Writes o directly in packed hi/lo bf16 layout for k5.
// grid (13, 256), 192 threads (ty=c-group of 16, tx=4 tokens)
// ============================================================
__global__ __launch_bounds__(192) void k4_av() {
    __shared__ float At[48][48];    // At[d][c] (transposed attn)
    const int bh = blockIdx.y;
    const int b = bh >> 3, h = bh & 7;
    const int tid = threadIdx.x;
    for (int i = tid; i < C_ * C_; i += 192) {
        int c = i / C_, d = i - (i / C_) * C_;
        At[d][c] = g_attn[(size_t)bh * C_ * C_ + i];
    }
    __syncthreads();

    const int ty = tid / 64;          // 0..2  -> c range [ty*16, ty*16+16)
    const int tx = tid - ty * 64;     // 0..63 -> tokens n0..n0+3
    const int n0 = blockIdx.x * 256 + tx * 4;
    if (n0 >= N_) return;

    const float* vp = g_v + (size_t)bh * C_ * N_ + n0;
    const int cb = ty * 16;
    float acc[16][4];
    #pragma unroll
    for (int c = 0; c < 16; c++)
        #pragma unroll
        for (int j = 0; j < 4; j++) acc[c][j] = 0.f;

    for (int d = 0; d < C_; d++) {
        float4 v4 = *(const float4*)(vp + (size_t)d * N_);
        float4 a0 = *(const float4*)&At[d][cb];
        float4 a1 = *(const float4*)&At[d][cb + 4];
        float4 a2 = *(const float4*)&At[d][cb + 8];
        float4 a3 = *(const float4*)&At[d][cb + 12];
        float as[16] = {a0.x,a0.y,a0.z,a0.w, a1.x,a1.y,a1.z,a1.w,
                        a2.x,a2.y,a2.z,a2.w, a3.x,a3.y,a3.z,a3.w};
        #pragma unroll
        for (int c = 0; c < 16; c++) {
            acc[c][0] += as[c] * v4.x;
            acc[c][1] += as[c] * v4.y;
            acc[c][2] += as[c] * v4.z;
            acc[c][3] += as[c] * v4.w;
        }
    }

    // write packed hi/lo bf16 into g_op for k5
    const int e0 = h * C_ + cb;       // multiple of 16
    const int chunk = e0 >> 5;
    const int off = e0 & 31;          // 0 or 16
    #pragma unroll
    for (int j = 0; j < 4; j++) {
        size_t m = (size_t)b * N_ + n0 + j;
        uint32_t hi[8], lo[8];
        #pragma unroll
        for (int p = 0; p < 8; p++) {
            float x0 = acc[2 * p][j], x1 = acc[2 * p + 1][j];
            __nv_bfloat162 hh = __floats2bfloat162_rn(x0, x1);
            float2 hf = __bfloat1622float2(hh);
            __nv_bfloat162 ll = __floats2bfloat162_rn(x0 - hf.x, x1 - hf.y);
            hi[p] = *reinterpret_cast<uint32_t*>(&hh);
            lo[p] = *reinterpret_cast<uint32_t*>(&ll);
        }
        __nv_bfloat16* base = g_op + m * 768 + chunk * 64;
        *(uint4*)(base + off)          = *(uint4*)&hi[0];
        *(uint4*)(base + off + 8)      = *(uint4*)&hi[4];
        *(uint4*)(base + 32 + off)     = *(uint4*)&lo[0];
        *(uint4*)(base + 32 + off + 8) = *(uint4*)&lo[4];
    }
}

// ============================================================
extern "C" void kernel_launch(void* const* d_in, const int* in_sizes, int n_in,
                              void* d_out, int out_size) {
    const float* x           = (const float*)d_in[0];
    const float* qkv_w       = (const float*)d_in[1];
    const float* temperature = (const float*)d_in[2];
    const float* proj_w      = (const float*)d_in[3];
    const float* proj_b      = (const float*)d_in[4];
    float* y = (float*)d_out;

    k0_split<<<(M_ * 96 + 255) / 256, 256>>>(x, 0, M_ * 96);
    k0_split<<<(E_ * 96 + 255) / 256, 256>>>(qkv_w, 1, E_ * 96);
    k0_split<<<(D_ * 96 + 255) / 256, 256>>>(proj_w, 2, D_ * 96);
    k1_mma<<<dim3(E_ / 128, M_ / 128), 256>>>();                 // (9, 784)
    k2_norms<<<(2 * BH_ * C_ + 7) / 8, 256>>>();
    k3_attn<<<BH_, 256>>>(temperature);
    k4_av<<<dim3((N_ + 255) / 256, BH_), 192>>>();               // (13, 256)
    k5_mma<<<dim3(D_ / 128, M_ / 128), 256>>>(proj_b, y);        // (3, 784)
}